// round 1
// baseline (speedup 1.0000x reference)
#include <cuda_runtime.h>
#include <cuda_bf16.h>
#include <cstdint>

// Problem constants (fixed by setup_inputs)
#define BATCH 4
#define MDIM 4096
#define NDIM 32
#define CDIM 256
#define DDIM 128
#define ROWS (BATCH * MDIM)        // 16384
#define LN_EPS 1e-5f
#define SCALE 0.08838834764831845f // 1/sqrt(128)

// ---------------- scratch (device globals, no allocation) ----------------
__device__ float g_M2[CDIM * CDIM];   // M[c][c'] * k_gamma[c']   (row-major [c][c'])
__device__ float g_bv2[CDIM];         // k_gamma[c'] * (Wk[c',:]·bq)
__device__ float g_rowvec[CDIM];      // mb[c] + u[c]  (for per-row bias dot)
__device__ float g_const[1];          // k_beta·bv + bq·bk
__device__ float g_lnx[ROWS * CDIM];  // LN(x)
__device__ float g_w[ROWS * CDIM];    // per-row weight vector w
__device__ float g_Bc[ROWS];          // per-row scalar bias

// ---------------- helpers ----------------
__device__ __forceinline__ float blockSum256(float v, float* s8) {
    // 256 threads, 8 warps; s8 has >= 8 floats. Returns total to ALL threads.
    #pragma unroll
    for (int o = 16; o; o >>= 1) v += __shfl_xor_sync(0xffffffffu, v, o);
    __syncthreads();                       // protect s8 reuse
    if ((threadIdx.x & 31) == 0) s8[threadIdx.x >> 5] = v;
    __syncthreads();
    float tot = 0.f;
    #pragma unroll
    for (int i = 0; i < 8; i++) tot += s8[i];
    return tot;
}

// ---------------- K1: prep M2, bv2, rowvec, const ----------------
__global__ void prep_kernel(const float* __restrict__ Wq, const float* __restrict__ Wk,
                            const float* __restrict__ bq, const float* __restrict__ bk,
                            const float* __restrict__ kg, const float* __restrict__ kb) {
    int c = blockIdx.x;            // 0..255
    int t = threadIdx.x;           // 0..255  (t == c')
    __shared__ float sq[DDIM];
    __shared__ float s8[8];
    if (t < DDIM) sq[t] = Wq[c * DDIM + t];
    __syncthreads();

    const float* wkr = Wk + t * DDIM;
    float acc = 0.f;
    #pragma unroll 4
    for (int d = 0; d < DDIM; d++) acc += sq[d] * wkr[d];

    g_M2[c * CDIM + t] = acc * kg[t];

    // mb[c] = sum_c' M[c,c'] * k_beta[c']
    float mb = blockSum256(acc * kb[t], s8);
    if (t == 0) {
        float u = 0.f;  // u[c] = sum_d Wq[c,d]*bk[d]
        #pragma unroll 4
        for (int d = 0; d < DDIM; d++) u += Wq[c * DDIM + d] * bk[d];
        g_rowvec[c] = mb + u;
    }

    if (c == 0) {
        // bv[c'] = Wk[c',:]·bq
        float bv = 0.f;
        #pragma unroll 4
        for (int d = 0; d < DDIM; d++) bv += wkr[d] * bq[d];
        g_bv2[t] = bv * kg[t];
        float cb = blockSum256(bv * kb[t], s8);
        if (t == 0) {
            float bb = 0.f;
            #pragma unroll 4
            for (int d = 0; d < DDIM; d++) bb += bq[d] * bk[d];
            g_const[0] = cb + bb;
        }
    }
}

// ---------------- K2: LN(x) + per-row bias dot ----------------
__global__ void ln_kernel(const float* __restrict__ x,
                          const float* __restrict__ qg, const float* __restrict__ qb) {
    int row = blockIdx.x;
    int t = threadIdx.x;           // 256 threads
    __shared__ float s8[8];
    float xv = x[row * CDIM + t];
    float s1 = blockSum256(xv, s8);
    float s2 = blockSum256(xv * xv, s8);
    float mu = s1 * (1.f / CDIM);
    float var = s2 * (1.f / CDIM) - mu * mu;
    float rs = rsqrtf(var + LN_EPS);
    float lnx = (xv - mu) * rs * qg[t] + qb[t];
    g_lnx[row * CDIM + t] = lnx;
    float dp = blockSum256(lnx * g_rowvec[t], s8);
    if (t == 0) g_Bc[row] = dp + g_const[0];
}

// ---------------- K3: GEMM  w = lnx(16384x256) @ M2(256x256) + bv2 ----------------
// 64x64 block tile, BK=16, 256 threads, 4x4 per thread
__global__ void gemm_kernel() {
    __shared__ __align__(16) float As[16][68];  // [k][m]
    __shared__ __align__(16) float Bs[16][68];  // [k][n]
    int bm = blockIdx.y * 64;
    int bn = blockIdx.x * 64;
    int tid = threadIdx.x;
    int tx = tid & 15, ty = tid >> 4;
    int ar = tid >> 2, aq = tid & 3;    // A tile: row 0..63, quad 0..3
    int br = tid >> 4, b4 = tid & 15;   // B tile: row 0..15, quad 0..15

    float acc[4][4];
    #pragma unroll
    for (int i = 0; i < 4; i++)
        #pragma unroll
        for (int j = 0; j < 4; j++) acc[i][j] = 0.f;

    for (int k0 = 0; k0 < CDIM; k0 += 16) {
        float4 av = *(const float4*)(g_lnx + (size_t)(bm + ar) * CDIM + k0 + aq * 4);
        As[aq * 4 + 0][ar] = av.x;
        As[aq * 4 + 1][ar] = av.y;
        As[aq * 4 + 2][ar] = av.z;
        As[aq * 4 + 3][ar] = av.w;
        float4 bvv = *(const float4*)(g_M2 + (size_t)(k0 + br) * CDIM + bn + b4 * 4);
        *(float4*)&Bs[br][b4 * 4] = bvv;
        __syncthreads();
        #pragma unroll
        for (int k = 0; k < 16; k++) {
            float4 a = *(const float4*)&As[k][ty * 4];
            float4 b = *(const float4*)&Bs[k][tx * 4];
            float ai[4] = {a.x, a.y, a.z, a.w};
            float bj[4] = {b.x, b.y, b.z, b.w};
            #pragma unroll
            for (int i = 0; i < 4; i++)
                #pragma unroll
                for (int j = 0; j < 4; j++) acc[i][j] += ai[i] * bj[j];
        }
        __syncthreads();
    }

    float4 bias = *(const float4*)(g_bv2 + bn + tx * 4);
    #pragma unroll
    for (int i = 0; i < 4; i++) {
        int row = bm + ty * 4 + i;
        float4 r;
        r.x = acc[i][0] + bias.x;
        r.y = acc[i][1] + bias.y;
        r.z = acc[i][2] + bias.z;
        r.w = acc[i][3] + bias.w;
        *(float4*)(g_w + (size_t)row * CDIM + bn + tx * 4) = r;
    }
}

// ---------------- K4: main streaming pass over y + softmax + z-sum ----------------
__global__ void attn_kernel(const float* __restrict__ y, const float* __restrict__ z,
                            float* __restrict__ out) {
    int row = blockIdx.x;          // b*M + m
    int tid = threadIdx.x;         // 256 threads
    __shared__ __align__(16) float sw[CDIM];
    __shared__ float s8[8];
    __shared__ float sdot[NDIM];

    float wv = g_w[(size_t)row * CDIM + tid];
    sw[tid] = wv;
    float G = blockSum256(wv, s8);   // contains syncthreads -> sw visible

    int n = tid >> 3, t8 = tid & 7;
    const float* yr = y + ((size_t)row * NDIM + n) * CDIM;
    float S1 = 0.f, S2 = 0.f, S3 = 0.f;
    #pragma unroll
    for (int j = 0; j < 8; j++) {
        int col = j * 32 + t8 * 4;
        float4 yv = *(const float4*)(yr + col);
        float4 w4 = *(const float4*)(sw + col);
        S1 += yv.x + yv.y + yv.z + yv.w;
        S2 += yv.x * yv.x + yv.y * yv.y + yv.z * yv.z + yv.w * yv.w;
        S3 += yv.x * w4.x + yv.y * w4.y + yv.z * w4.z + yv.w * w4.w;
    }
    #pragma unroll
    for (int o = 4; o; o >>= 1) {
        S1 += __shfl_down_sync(0xffffffffu, S1, o);
        S2 += __shfl_down_sync(0xffffffffu, S2, o);
        S3 += __shfl_down_sync(0xffffffffu, S3, o);
    }
    if (t8 == 0) {
        float mu = S1 * (1.f / CDIM);
        float var = S2 * (1.f / CDIM) - mu * mu;
        float rs = rsqrtf(var + LN_EPS);
        float Bc = g_Bc[row];
        sdot[n] = SCALE * (rs * (S3 - mu * G) + Bc);
    }
    __syncthreads();
    if (tid < NDIM) {
        float v = sdot[tid];
        float m = v;
        #pragma unroll
        for (int o = 16; o; o >>= 1) m = fmaxf(m, __shfl_xor_sync(0xffffffffu, m, o));
        float e = expf(v - m);
        float zb = z[(size_t)row * NDIM + tid];
        float se = e, sez = e * zb;
        #pragma unroll
        for (int o = 16; o; o >>= 1) {
            se += __shfl_xor_sync(0xffffffffu, se, o);
            sez += __shfl_xor_sync(0xffffffffu, sez, o);
        }
        if (tid == 0) out[row] = sez / se;
    }
}

// ---------------- launch ----------------
extern "C" void kernel_launch(void* const* d_in, const int* in_sizes, int n_in,
                              void* d_out, int out_size) {
    const float* x  = (const float*)d_in[0];
    const float* y  = (const float*)d_in[1];
    const float* z  = (const float*)d_in[2];
    const float* qg = (const float*)d_in[3];
    const float* qb = (const float*)d_in[4];
    const float* Wq = (const float*)d_in[5];
    const float* bq = (const float*)d_in[6];
    const float* kg = (const float*)d_in[7];
    const float* kb = (const float*)d_in[8];
    const float* Wk = (const float*)d_in[9];
    const float* bk = (const float*)d_in[10];
    float* out = (float*)d_out;

    prep_kernel<<<CDIM, 256>>>(Wq, Wk, bq, bk, kg, kb);
    ln_kernel<<<ROWS, 256>>>(x, qg, qb);
    gemm_kernel<<<dim3(CDIM / 64, ROWS / 64), 256>>>();
    attn_kernel<<<ROWS, 256>>>(y, z, out);
}

// round 2
// speedup vs baseline: 1.0460x; 1.0460x over previous
#include <cuda_runtime.h>
#include <cuda_bf16.h>
#include <cstdint>

// Problem constants (fixed by setup_inputs)
#define BATCH 4
#define MDIM 4096
#define NDIM 32
#define CDIM 256
#define DDIM 128
#define ROWS (BATCH * MDIM)        // 16384
#define LN_EPS 1e-5f
#define SCALE 0.08838834764831845f // 1/sqrt(128)

// ---------------- scratch (device globals, no allocation) ----------------
__device__ float g_M2[CDIM * CDIM];   // (Wq Wk^T)[c][c'] * k_gamma[c']
__device__ float g_bv2[CDIM];         // k_gamma[c'] * (Wk[c',:]·bq)
__device__ float g_rowvec[CDIM];      // mb[c] + u[c]
__device__ float g_const[1];          // k_beta·bv + bq·bk
__device__ float g_e[CDIM];           // q_gamma ⊙ rowvec
__device__ float g_EF[2];             // {E = Σe, F + const}
__device__ float2 g_stat[ROWS];       // {mu, rs} per row of x
__device__ float g_w[ROWS * CDIM];    // per-row weight vector w
__device__ float g_Bc[ROWS];          // per-row scalar bias

// ---------------- helpers ----------------
__device__ __forceinline__ float blockSum256(float v, float* s8) {
    #pragma unroll
    for (int o = 16; o; o >>= 1) v += __shfl_xor_sync(0xffffffffu, v, o);
    __syncthreads();
    if ((threadIdx.x & 31) == 0) s8[threadIdx.x >> 5] = v;
    __syncthreads();
    float tot = 0.f;
    #pragma unroll
    for (int i = 0; i < 8; i++) tot += s8[i];
    return tot;
}

#define FMA2(d, a, b) \
    asm("fma.rn.f32x2 %0, %1, %2, %0;" : "+l"(d) : "l"(a), "l"(b))
#define PACK2(out, lo, hi) \
    asm("mov.b64 %0, {%1, %2};" : "=l"(out) : "r"(__float_as_uint(lo)), "r"(__float_as_uint(hi)))

__device__ __forceinline__ float2 unpack2(unsigned long long v) {
    unsigned int lo, hi;
    asm("mov.b64 {%0, %1}, %2;" : "=r"(lo), "=r"(hi) : "l"(v));
    return make_float2(__uint_as_float(lo), __uint_as_float(hi));
}

// ---------------- K1: prep M2, bv2, rowvec, const ----------------
__global__ void prep_kernel(const float* __restrict__ Wq, const float* __restrict__ Wk,
                            const float* __restrict__ bq, const float* __restrict__ bk,
                            const float* __restrict__ kg, const float* __restrict__ kb) {
    int c = blockIdx.x;            // 0..255
    int t = threadIdx.x;           // 0..255  (t == c')
    __shared__ float sq[DDIM];
    __shared__ float s8[8];
    if (t < DDIM) sq[t] = Wq[c * DDIM + t];
    __syncthreads();

    const float* wkr = Wk + t * DDIM;
    float acc = 0.f;
    #pragma unroll 4
    for (int d = 0; d < DDIM; d++) acc += sq[d] * wkr[d];

    g_M2[c * CDIM + t] = acc * kg[t];

    float mb = blockSum256(acc * kb[t], s8);
    if (t == 0) {
        float u = 0.f;
        #pragma unroll 4
        for (int d = 0; d < DDIM; d++) u += Wq[c * DDIM + d] * bk[d];
        g_rowvec[c] = mb + u;
    }

    if (c == 0) {
        float bv = 0.f;
        #pragma unroll 4
        for (int d = 0; d < DDIM; d++) bv += wkr[d] * bq[d];
        g_bv2[t] = bv * kg[t];
        float cb = blockSum256(bv * kb[t], s8);
        if (t == 0) {
            float bb = 0.f;
            #pragma unroll 4
            for (int d = 0; d < DDIM; d++) bb += bq[d] * bk[d];
            g_const[0] = cb + bb;
        }
    }
}

// ---------------- K1b: e = qg*rowvec, E, F ----------------
__global__ void prep2_kernel(const float* __restrict__ qg, const float* __restrict__ qb) {
    int t = threadIdx.x;
    __shared__ float s8[8];
    float rv = g_rowvec[t];
    float e = qg[t] * rv;
    g_e[t] = e;
    float E = blockSum256(e, s8);
    float F = blockSum256(qb[t] * rv, s8);
    if (t == 0) { g_EF[0] = E; g_EF[1] = F + g_const[0]; }
}

// ---------------- K2: per-row stats of x + Bc ----------------
__global__ void stats_kernel(const float* __restrict__ x) {
    int row = blockIdx.x;
    int t = threadIdx.x;
    __shared__ float s8[8];
    float xv = x[(size_t)row * CDIM + t];
    float s1 = blockSum256(xv, s8);
    float s2 = blockSum256(xv * xv, s8);
    float s3 = blockSum256(xv * g_e[t], s8);
    float mu = s1 * (1.f / CDIM);
    float var = s2 * (1.f / CDIM) - mu * mu;
    float rs = rsqrtf(var + LN_EPS);
    if (t == 0) {
        g_stat[row] = make_float2(mu, rs);
        g_Bc[row] = rs * (s3 - mu * g_EF[0]) + g_EF[1];
    }
}

// ---------------- K3: GEMM  w = LN(x)(16384x256) @ M2(256x256) + bv2 ----------------
// 128x128 tile, BK=16, 256 threads, 8x8 per thread, packed f32x2 FMAs.
// LN applied on the fly while staging A.
__global__ void __launch_bounds__(256, 2)
gemm_kernel(const float* __restrict__ x,
            const float* __restrict__ qg, const float* __restrict__ qb) {
    __shared__ __align__(16) float As[16][132];  // [k][m]
    __shared__ __align__(16) float Bs[16][128];  // [k][n]

    const int bm = blockIdx.y * 128;
    const int bn = blockIdx.x * 128;
    const int tid = threadIdx.x;
    const int tx = tid & 15;          // n-group (8 cols)
    const int ty = tid >> 4;          // m-group (8 rows)

    // A staging: rows r0, r0+64; k-quad q (4 floats)
    const int r0 = tid >> 2;
    const int aq = tid & 3;
    // B staging: k-row kr, kr+8; col quad c4 (two float4: c4, c4+16)
    const int kr = tid >> 5;          // 0..7
    const int c4 = tid & 31;          // 0..31

    float2 st0 = g_stat[bm + r0];
    float2 st1 = g_stat[bm + r0 + 64];

    unsigned long long acc[8][4];
    #pragma unroll
    for (int i = 0; i < 8; i++)
        #pragma unroll
        for (int j = 0; j < 4; j++) acc[i][j] = 0ull;

    for (int k0 = 0; k0 < CDIM; k0 += 16) {
        // --- stage A with fused LayerNorm ---
        float4 gq = *(const float4*)(qg + k0 + aq * 4);
        float4 gb = *(const float4*)(qb + k0 + aq * 4);
        {
            float4 xa = *(const float4*)(x + (size_t)(bm + r0) * CDIM + k0 + aq * 4);
            float t0 = st0.y * gq.x, t1 = st0.y * gq.y, t2 = st0.y * gq.z, t3 = st0.y * gq.w;
            As[aq * 4 + 0][r0] = fmaf(xa.x, t0, gb.x - st0.x * t0);
            As[aq * 4 + 1][r0] = fmaf(xa.y, t1, gb.y - st0.x * t1);
            As[aq * 4 + 2][r0] = fmaf(xa.z, t2, gb.z - st0.x * t2);
            As[aq * 4 + 3][r0] = fmaf(xa.w, t3, gb.w - st0.x * t3);
        }
        {
            float4 xa = *(const float4*)(x + (size_t)(bm + r0 + 64) * CDIM + k0 + aq * 4);
            float t0 = st1.y * gq.x, t1 = st1.y * gq.y, t2 = st1.y * gq.z, t3 = st1.y * gq.w;
            As[aq * 4 + 0][r0 + 64] = fmaf(xa.x, t0, gb.x - st1.x * t0);
            As[aq * 4 + 1][r0 + 64] = fmaf(xa.y, t1, gb.y - st1.x * t1);
            As[aq * 4 + 2][r0 + 64] = fmaf(xa.z, t2, gb.z - st1.x * t2);
            As[aq * 4 + 3][r0 + 64] = fmaf(xa.w, t3, gb.w - st1.x * t3);
        }
        // --- stage B ---
        *(float4*)&Bs[kr][(c4 & 15) * 4 + (c4 >> 4) * 64] =
            *(const float4*)(g_M2 + (size_t)(k0 + kr) * CDIM + bn + (c4 & 15) * 4 + (c4 >> 4) * 64);
        *(float4*)&Bs[kr + 8][(c4 & 15) * 4 + (c4 >> 4) * 64] =
            *(const float4*)(g_M2 + (size_t)(k0 + kr + 8) * CDIM + bn + (c4 & 15) * 4 + (c4 >> 4) * 64);
        __syncthreads();

        #pragma unroll
        for (int k = 0; k < 16; k++) {
            float4 a0 = *(const float4*)&As[k][ty * 8];
            float4 a1 = *(const float4*)&As[k][ty * 8 + 4];
            const unsigned long long* bp = (const unsigned long long*)&Bs[k][tx * 8];
            unsigned long long b0 = bp[0], b1 = bp[1], b2 = bp[2], b3 = bp[3];
            float av[8] = {a0.x, a0.y, a0.z, a0.w, a1.x, a1.y, a1.z, a1.w};
            #pragma unroll
            for (int i = 0; i < 8; i++) {
                unsigned long long aa;
                PACK2(aa, av[i], av[i]);
                FMA2(acc[i][0], aa, b0);
                FMA2(acc[i][1], aa, b1);
                FMA2(acc[i][2], aa, b2);
                FMA2(acc[i][3], aa, b3);
            }
        }
        __syncthreads();
    }

    float4 bias0 = *(const float4*)(g_bv2 + bn + tx * 8);
    float4 bias1 = *(const float4*)(g_bv2 + bn + tx * 8 + 4);
    #pragma unroll
    for (int i = 0; i < 8; i++) {
        int row = bm + ty * 8 + i;
        float2 p0 = unpack2(acc[i][0]);
        float2 p1 = unpack2(acc[i][1]);
        float2 p2 = unpack2(acc[i][2]);
        float2 p3 = unpack2(acc[i][3]);
        float4 r0v = make_float4(p0.x + bias0.x, p0.y + bias0.y, p1.x + bias0.z, p1.y + bias0.w);
        float4 r1v = make_float4(p2.x + bias1.x, p2.y + bias1.y, p3.x + bias1.z, p3.y + bias1.w);
        *(float4*)(g_w + (size_t)row * CDIM + bn + tx * 8) = r0v;
        *(float4*)(g_w + (size_t)row * CDIM + bn + tx * 8 + 4) = r1v;
    }
}

// ---------------- K4: main streaming pass over y + softmax + z-sum ----------------
__global__ void attn_kernel(const float* __restrict__ y, const float* __restrict__ z,
                            float* __restrict__ out) {
    int row = blockIdx.x;          // b*M + m
    int tid = threadIdx.x;         // 256 threads
    __shared__ __align__(16) float sw[CDIM];
    __shared__ float s8[8];
    __shared__ float sdot[NDIM];

    float wv = g_w[(size_t)row * CDIM + tid];
    sw[tid] = wv;
    float G = blockSum256(wv, s8);   // includes syncthreads -> sw visible

    int n = tid >> 3, t8 = tid & 7;
    const float* yr = y + ((size_t)row * NDIM + n) * CDIM;
    float S1 = 0.f, S2 = 0.f, S3 = 0.f;
    #pragma unroll
    for (int j = 0; j < 8; j++) {
        int col = j * 32 + t8 * 4;
        float4 yv = __ldcs((const float4*)(yr + col));
        float4 w4 = *(const float4*)(sw + col);
        S1 += yv.x + yv.y + yv.z + yv.w;
        S2 += yv.x * yv.x + yv.y * yv.y + yv.z * yv.z + yv.w * yv.w;
        S3 += yv.x * w4.x + yv.y * w4.y + yv.z * w4.z + yv.w * w4.w;
    }
    #pragma unroll
    for (int o = 4; o; o >>= 1) {
        S1 += __shfl_down_sync(0xffffffffu, S1, o);
        S2 += __shfl_down_sync(0xffffffffu, S2, o);
        S3 += __shfl_down_sync(0xffffffffu, S3, o);
    }
    if (t8 == 0) {
        float mu = S1 * (1.f / CDIM);
        float var = S2 * (1.f / CDIM) - mu * mu;
        float rs = rsqrtf(var + LN_EPS);
        float Bc = g_Bc[row];
        sdot[n] = SCALE * (rs * (S3 - mu * G) + Bc);
    }
    __syncthreads();
    if (tid < NDIM) {
        float v = sdot[tid];
        float m = v;
        #pragma unroll
        for (int o = 16; o; o >>= 1) m = fmaxf(m, __shfl_xor_sync(0xffffffffu, m, o));
        float e = expf(v - m);
        float zb = z[(size_t)row * NDIM + tid];
        float se = e, sez = e * zb;
        #pragma unroll
        for (int o = 16; o; o >>= 1) {
            se += __shfl_xor_sync(0xffffffffu, se, o);
            sez += __shfl_xor_sync(0xffffffffu, sez, o);
        }
        if (tid == 0) out[row] = sez / se;
    }
}

// ---------------- launch ----------------
extern "C" void kernel_launch(void* const* d_in, const int* in_sizes, int n_in,
                              void* d_out, int out_size) {
    const float* x  = (const float*)d_in[0];
    const float* y  = (const float*)d_in[1];
    const float* z  = (const float*)d_in[2];
    const float* qg = (const float*)d_in[3];
    const float* qb = (const float*)d_in[4];
    const float* Wq = (const float*)d_in[5];
    const float* bq = (const float*)d_in[6];
    const float* kg = (const float*)d_in[7];
    const float* kb = (const float*)d_in[8];
    const float* Wk = (const float*)d_in[9];
    const float* bk = (const float*)d_in[10];
    float* out = (float*)d_out;

    prep_kernel<<<CDIM, 256>>>(Wq, Wk, bq, bk, kg, kb);
    prep2_kernel<<<1, 256>>>(qg, qb);
    stats_kernel<<<ROWS, 256>>>(x);
    gemm_kernel<<<dim3(CDIM / 128, ROWS / 128), 256>>>(x, qg, qb);
    attn_kernel<<<ROWS, 256>>>(y, z, out);
}